// round 1
// baseline (speedup 1.0000x reference)
#include <cuda_runtime.h>
#include <cstdint>
#include <cstddef>

// Problem dims
#define B_    64
#define S_    1024
#define I_    512
#define H_    512
#define G4H   2048
#define M_TOT (B_ * S_)        // 65536

// ---------------- device scratch (no allocations allowed) ----------------
__device__ float    g_xproj[(size_t)S_ * B_ * G4H];   // 512 MB, layout (S, B, 4H)
__device__ float    g_hbuf[2][B_ * H_];               // ping-pong h
__device__ float    g_bias[G4H];
__device__ unsigned g_count;                          // grid barrier counter

// =====================================================================
// prep: combined bias + barrier counter reset (runs before scan, so the
// persistent kernel always starts each launch with g_count == 0)
// =====================================================================
__global__ void prep_kernel(const float* __restrict__ b_ii, const float* __restrict__ b_if,
                            const float* __restrict__ b_ig, const float* __restrict__ b_io,
                            const float* __restrict__ b_hi, const float* __restrict__ b_hf,
                            const float* __restrict__ b_hg, const float* __restrict__ b_ho)
{
    int gidx = blockIdx.x * blockDim.x + threadIdx.x;
    if (gidx == 0) g_count = 0u;
    if (gidx < G4H) {
        int j   = gidx & (H_ - 1);
        int sel = gidx >> 9;
        float v;
        if      (sel == 0) v = b_ii[j] + b_hi[j];
        else if (sel == 1) v = b_if[j] + b_hf[j];
        else if (sel == 2) v = b_ig[j] + b_hg[j];
        else               v = b_io[j] + b_ho[j];
        g_bias[gidx] = v;
    }
}

// =====================================================================
// x_proj GEMM: C[m][n] = sum_k A[m][k] * W[n][k] + bias[n]
// A = inputs (65536 x 512), W = stacked {w_ii,w_if,w_ig,w_io} (2048 x 512)
// Output scattered into g_xproj laid out (t, b, 4H) with m = b*S + t.
// 128x128x16 tiles, 256 threads, 8x8 microtiles, reg-prefetch pipeline.
// =====================================================================
#define GM 128
#define GN 128
#define GK 16

__global__ __launch_bounds__(256, 2)
void xproj_gemm(const float* __restrict__ A,
                const float* __restrict__ w_ii, const float* __restrict__ w_if,
                const float* __restrict__ w_ig, const float* __restrict__ w_io)
{
    __shared__ float sA[GK][GM + 4];
    __shared__ float sB[GK][GN + 4];

    const int tid   = threadIdx.x;
    const int mBase = blockIdx.y * GM;
    const int nBase = blockIdx.x * GN;   // each N-tile lies fully inside one weight matrix
    const float* W = (nBase < 512) ? w_ii : (nBase < 1024) ? w_if : (nBase < 1536) ? w_ig : w_io;
    const int jBase = nBase & (H_ - 1);

    const int lrow = tid >> 1;           // 0..127
    const int lk   = (tid & 1) << 3;     // 0 or 8
    const float* Ar = A + (size_t)(mBase + lrow) * I_ + lk;
    const float* Br = W + (size_t)(jBase + lrow) * I_ + lk;

    const int tx = tid & 15;
    const int ty = tid >> 4;

    float acc[8][8];
#pragma unroll
    for (int i = 0; i < 8; i++)
#pragma unroll
        for (int j = 0; j < 8; j++) acc[i][j] = 0.0f;

    // prefetch first K-slice into registers
    float4 a0 = *(const float4*)(Ar);
    float4 a1 = *(const float4*)(Ar + 4);
    float4 b0 = *(const float4*)(Br);
    float4 b1 = *(const float4*)(Br + 4);

    for (int k0 = 0; k0 < I_; k0 += GK) {
        // stage registers -> shared (transposed)
        sA[lk + 0][lrow] = a0.x; sA[lk + 1][lrow] = a0.y;
        sA[lk + 2][lrow] = a0.z; sA[lk + 3][lrow] = a0.w;
        sA[lk + 4][lrow] = a1.x; sA[lk + 5][lrow] = a1.y;
        sA[lk + 6][lrow] = a1.z; sA[lk + 7][lrow] = a1.w;
        sB[lk + 0][lrow] = b0.x; sB[lk + 1][lrow] = b0.y;
        sB[lk + 2][lrow] = b0.z; sB[lk + 3][lrow] = b0.w;
        sB[lk + 4][lrow] = b1.x; sB[lk + 5][lrow] = b1.y;
        sB[lk + 6][lrow] = b1.z; sB[lk + 7][lrow] = b1.w;
        __syncthreads();

        // prefetch next K-slice while computing this one
        if (k0 + GK < I_) {
            a0 = *(const float4*)(Ar + k0 + GK);
            a1 = *(const float4*)(Ar + k0 + GK + 4);
            b0 = *(const float4*)(Br + k0 + GK);
            b1 = *(const float4*)(Br + k0 + GK + 4);
        }

#pragma unroll
        for (int kk = 0; kk < GK; kk++) {
            float ar[8], br[8];
            *(float4*)(ar)     = *(const float4*)(&sA[kk][ty * 4]);
            *(float4*)(ar + 4) = *(const float4*)(&sA[kk][64 + ty * 4]);
            *(float4*)(br)     = *(const float4*)(&sB[kk][tx * 4]);
            *(float4*)(br + 4) = *(const float4*)(&sB[kk][64 + tx * 4]);
#pragma unroll
            for (int i = 0; i < 8; i++)
#pragma unroll
                for (int j = 0; j < 8; j++)
                    acc[i][j] += ar[i] * br[j];
        }
        __syncthreads();
    }

    // epilogue: add bias, scatter to (t, b, 4H)
    float4 bias0 = *(const float4*)(g_bias + nBase + tx * 4);
    float4 bias1 = *(const float4*)(g_bias + nBase + 64 + tx * 4);
#pragma unroll
    for (int i = 0; i < 8; i++) {
        int ml = (i < 4) ? (ty * 4 + i) : (64 + ty * 4 + (i - 4));
        int m  = mBase + ml;
        int b  = m >> 10;          // m = b*S + t
        int t  = m & (S_ - 1);
        float* dst = g_xproj + ((size_t)t * B_ + b) * G4H + nBase;
        float4 v0, v1;
        v0.x = acc[i][0] + bias0.x; v0.y = acc[i][1] + bias0.y;
        v0.z = acc[i][2] + bias0.z; v0.w = acc[i][3] + bias0.w;
        v1.x = acc[i][4] + bias1.x; v1.y = acc[i][5] + bias1.y;
        v1.z = acc[i][6] + bias1.z; v1.w = acc[i][7] + bias1.w;
        *(float4*)(dst + tx * 4)      = v0;
        *(float4*)(dst + 64 + tx * 4) = v1;
    }
}

// =====================================================================
// Persistent LSTM scan.
// 128 CTAs (1/SM guaranteed resident), 256 threads.
// CTA owns hidden units j0..j0+3 for all 4 gates -> 16 gate rows.
// Wh slice kept in shared for the whole scan; h staged to shared each step.
// c state lives in registers (one thread per (b, j) pair).
// Software grid barrier per step (monotone counter, reset by prep kernel).
// =====================================================================
#define SCAN_CTAS    128
#define SCAN_THREADS 256
#define HPAD         516   // padded row stride (floats): conflict-free float4 reads
#define SW_FLOATS    (16 * HPAD)
#define SH_FLOATS    (64 * HPAD)
#define SG_FLOATS    (64 * 17)
#define SMEM_FLOATS  (SW_FLOATS + SH_FLOATS + SG_FLOATS)
#define SMEM_BYTES   (SMEM_FLOATS * 4)

__device__ __forceinline__ float sigmoidf_(float x) { return 1.0f / (1.0f + expf(-x)); }

__global__ __launch_bounds__(SCAN_THREADS, 1)
void lstm_scan(const float* __restrict__ h0, const float* __restrict__ c0,
               const float* __restrict__ w_hi, const float* __restrict__ w_hf,
               const float* __restrict__ w_hg, const float* __restrict__ w_ho,
               float* __restrict__ out)
{
    extern __shared__ float sm[];
    float* sW = sm;                       // [16][HPAD]
    float* sH = sm + SW_FLOATS;           // [64][HPAD]
    float* sG = sm + SW_FLOATS + SH_FLOATS; // [64][17]

    const int tid = threadIdx.x;
    const int cta = blockIdx.x;
    const int j0  = cta * 4;

    // load this CTA's Wh slice (16 rows x 512) into shared, once
    for (int idx = tid; idx < 16 * 512; idx += SCAN_THREADS) {
        int r = idx >> 9;
        int k = idx & 511;
        int gsel = r >> 2;
        int j = j0 + (r & 3);
        const float* w = (gsel == 0) ? w_hi : (gsel == 1) ? w_hf : (gsel == 2) ? w_hg : w_ho;
        sW[r * HPAD + k] = w[(size_t)j * H_ + k];
    }

    // dot-phase mapping: thread -> batches {bq, bq+32}, rows {rq, rq+8}
    const int bq = tid >> 3;
    const int rq = tid & 7;
    // elementwise mapping: thread -> (eb, ej)
    const int eb  = tid >> 2;
    const int ejl = tid & 3;
    const int ej  = j0 + ejl;

    float c_reg = c0[eb * H_ + ej];

    const float4* sH4 = (const float4*)sH;
    const float4* sW4 = (const float4*)sW;

    for (int t = 0; t < S_; t++) {
        // ---- stage h(t-1) into shared (L2-coherent reads: __ldcg) ----
        const float4* hsrc4 = (t == 0) ? (const float4*)h0
                                       : (const float4*)g_hbuf[(t - 1) & 1];
#pragma unroll
        for (int i = 0; i < 32; i++) {
            int idx4 = tid + i * SCAN_THREADS;   // 0..8191 (64*128 float4)
            int bb   = idx4 >> 7;
            int kk4  = idx4 & 127;
            float4 v = __ldcg(&hsrc4[idx4]);
            ((float4*)sH)[bb * 129 + kk4] = v;   // HPAD/4 == 129
        }
        // prefetch x_proj contributions for the elementwise phase
        const float* xr = g_xproj + ((size_t)t * B_ + eb) * G4H + ej;
        float xpi = xr[0], xpf = xr[512], xpg = xr[1024], xpo = xr[1536];
        __syncthreads();

        // ---- dot phase: gates_partial = h @ Wh_slice^T ----
        const float4* hA = sH4 + (size_t)bq * 129;
        const float4* hB = sH4 + (size_t)(bq + 32) * 129;
        const float4* wA = sW4 + (size_t)rq * 129;
        const float4* wB = sW4 + (size_t)(rq + 8) * 129;
        float a00 = 0.f, a01 = 0.f, a10 = 0.f, a11 = 0.f;
#pragma unroll 8
        for (int k4 = 0; k4 < 128; k4++) {
            float4 h0v = hA[k4], h1v = hB[k4];
            float4 w0v = wA[k4], w1v = wB[k4];
            a00 += h0v.x * w0v.x + h0v.y * w0v.y + h0v.z * w0v.z + h0v.w * w0v.w;
            a01 += h0v.x * w1v.x + h0v.y * w1v.y + h0v.z * w1v.z + h0v.w * w1v.w;
            a10 += h1v.x * w0v.x + h1v.y * w0v.y + h1v.z * w0v.z + h1v.w * w0v.w;
            a11 += h1v.x * w1v.x + h1v.y * w1v.y + h1v.z * w1v.z + h1v.w * w1v.w;
        }
        sG[bq * 17 + rq]            = a00;
        sG[bq * 17 + rq + 8]        = a01;
        sG[(bq + 32) * 17 + rq]     = a10;
        sG[(bq + 32) * 17 + rq + 8] = a11;
        __syncthreads();

        // ---- elementwise LSTM cell update ----
        float gi = sG[eb * 17 + 0  + ejl] + xpi;
        float gf = sG[eb * 17 + 4  + ejl] + xpf;
        float gg = sG[eb * 17 + 8  + ejl] + xpg;
        float go = sG[eb * 17 + 12 + ejl] + xpo;
        float it = sigmoidf_(gi);
        float ft = sigmoidf_(gf);
        float gt = tanhf(gg);
        float ot = sigmoidf_(go);
        c_reg = ft * c_reg + it * gt;
        float hv = ot * tanhf(c_reg);

        g_hbuf[t & 1][eb * H_ + ej] = hv;
        out[((size_t)eb * S_ + t) * H_ + ej] = hv;
        if (t == S_ - 1) {
            out[(size_t)B_ * S_ * H_ + eb * H_ + ej]            = hv;     // h_f
            out[(size_t)B_ * S_ * H_ + B_ * H_ + eb * H_ + ej]  = c_reg;  // c_f
        }

        // ---- grid barrier (monotone counter; target = (t+1)*gridDim) ----
        __syncthreads();
        if (tid == 0) {
            __threadfence();
            atomicAdd(&g_count, 1u);
            unsigned target = (unsigned)(t + 1) * (unsigned)SCAN_CTAS;
            while (*(volatile unsigned*)&g_count < target) { }
            __threadfence();
        }
        __syncthreads();
    }
}

// =====================================================================
extern "C" void kernel_launch(void* const* d_in, const int* in_sizes, int n_in,
                              void* d_out, int out_size)
{
    const float* inputs = (const float*)d_in[0];
    const float* h0     = (const float*)d_in[1];
    const float* c0     = (const float*)d_in[2];
    const float* w_ii   = (const float*)d_in[3];
    const float* w_if   = (const float*)d_in[4];
    const float* w_ig   = (const float*)d_in[5];
    const float* w_io   = (const float*)d_in[6];
    const float* w_hi   = (const float*)d_in[7];
    const float* w_hf   = (const float*)d_in[8];
    const float* w_hg   = (const float*)d_in[9];
    const float* w_ho   = (const float*)d_in[10];
    const float* b_ii   = (const float*)d_in[11];
    const float* b_if   = (const float*)d_in[12];
    const float* b_ig   = (const float*)d_in[13];
    const float* b_io   = (const float*)d_in[14];
    const float* b_hi   = (const float*)d_in[15];
    const float* b_hf   = (const float*)d_in[16];
    const float* b_ho   = (const float*)d_in[17];  // dict order: b_ho before b_hg
    const float* b_hg   = (const float*)d_in[18];
    float* out = (float*)d_out;

    cudaFuncSetAttribute(lstm_scan, cudaFuncAttributeMaxDynamicSharedMemorySize, SMEM_BYTES);

    prep_kernel<<<4, 512>>>(b_ii, b_if, b_ig, b_io, b_hi, b_hf, b_hg, b_ho);
    xproj_gemm<<<dim3(G4H / GN, M_TOT / GM), 256>>>(inputs, w_ii, w_if, w_ig, w_io);
    lstm_scan<<<SCAN_CTAS, SCAN_THREADS, SMEM_BYTES>>>(h0, c0, w_hi, w_hf, w_hg, w_ho, out);
}